// round 2
// baseline (speedup 1.0000x reference)
#include <cuda_runtime.h>

// AdaptAttention: b=16, H=8 (4 global + 4 local), N=1024, DK=64, fp32.
// Outputs concatenated: out (16,8,1024,64), p_attn_g (16,4,1024,1024), p_attn_l (16,4,1024,1024).

#define NNq  1024
#define DKq  64
#define SCALEq 0.125f
#define NEGBIG -1000000000000.0f

// ---- device scratch (no allocations allowed) ----
__device__ float g_W2[512 * 4];        // sum_d upw[c, hl*64+d] * mlpw[hl,d]
__device__ float g_bias2[4];
__device__ float g_R[4 * 2047];        // rel-pos reweight, delta-indexed
__device__ float g_rowadd[16 * 4 * 1024]; // vv+uu+bias2+mlp_b  per (b,hl,q)
__device__ float g_coladd[16 * 4 * 1024]; // vv                 per (b,hl,k)

__global__ void prep_w2(const float* __restrict__ upw,
                        const float* __restrict__ upb,
                        const float* __restrict__ mlpw) {
    int t = blockIdx.x * blockDim.x + threadIdx.x;
    if (t < 512) {
        const float* row = upw + (size_t)t * 256;
        float s0 = 0.f, s1 = 0.f, s2 = 0.f, s3 = 0.f;
        for (int d = 0; d < 64; ++d) {
            s0 += row[d]       * mlpw[d];
            s1 += row[64 + d]  * mlpw[64 + d];
            s2 += row[128 + d] * mlpw[128 + d];
            s3 += row[192 + d] * mlpw[192 + d];
        }
        g_W2[t * 4 + 0] = s0;
        g_W2[t * 4 + 1] = s1;
        g_W2[t * 4 + 2] = s2;
        g_W2[t * 4 + 3] = s3;
    }
    if (t < 4) {
        float s = 0.f;
        for (int d = 0; d < 64; ++d) s += upb[t * 64 + d] * mlpw[t * 64 + d];
        g_bias2[t] = s;
    }
}

__global__ void prep_r(const float* __restrict__ rpt,
                       const float* __restrict__ mlpw) {
    int idx = blockIdx.x * blockDim.x + threadIdx.x;
    if (idx >= 4 * 2047) return;
    int hl = idx / 2047, delta = idx % 2047;
    const float* row = rpt + (size_t)delta * 256 + hl * 64;
    const float* w = mlpw + hl * 64;
    float s = 0.f;
    for (int d = 0; d < 64; ++d) s += row[d] * w[d];
    g_R[idx] = s;   // layout [hl][delta]
}

__global__ void prep_rc(const float* __restrict__ value,
                        const float* __restrict__ users,
                        const float* __restrict__ mlpw,
                        const float* __restrict__ mlpb) {
    int idx = blockIdx.x * blockDim.x + threadIdx.x; // < 16*4*1024
    int i  = idx & 1023;
    int hl = (idx >> 10) & 3;
    int b  = idx >> 12;
    const float* vrow = value + (((size_t)(b * 8 + 4 + hl)) * NNq + i) * 64;
    const float* w = mlpw + hl * 64;
    float vv = 0.f;
    for (int d = 0; d < 64; ++d) vv += vrow[d] * w[d];
    const float* urow = users + ((size_t)b * NNq + i) * 512;
    float uu = 0.f;
    for (int c = 0; c < 512; ++c) uu += urow[c] * g_W2[c * 4 + hl];
    g_coladd[idx] = vv;
    g_rowadd[idx] = vv + uu + g_bias2[hl] + mlpb[hl];
}

// ---- main attention kernel ----
// CTA: 256 threads (8 warps), 16 q rows (2 rows/warp), 128-key K/V tiles.
// smem: ksh[128][68] (pad->conflict-free), ssh[16][1024] scores->p, qsh[16][64], rowc[16].
#define KSTRIDE 68
#define SM_KSH  (128 * KSTRIDE)              // 8704 floats
#define SM_SSH  (16 * 1024)                  // 16384 floats
#define SM_QSH  (16 * 64)                    // 1024 floats
#define SMEM_FLOATS (SM_KSH + SM_SSH + SM_QSH + 32)
#define SMEM_BYTES  (SMEM_FLOATS * 4)        // 104,704 B -> 2 CTAs/SM

__global__ void __launch_bounds__(256, 2)
attn_kernel(const float* __restrict__ qg, const float* __restrict__ kg,
            const float* __restrict__ vg, const int* __restrict__ mask,
            float* __restrict__ out, float* __restrict__ pg, float* __restrict__ pl) {
    extern __shared__ float sm[];
    float* ksh  = sm;
    float* ssh  = sm + SM_KSH;
    float* qsh  = sm + SM_KSH + SM_SSH;
    float* rowc = sm + SM_KSH + SM_SSH + SM_QSH;

    const int tid  = threadIdx.x;
    const int warp = tid >> 5;
    const int lane = tid & 31;
    const int bh = blockIdx.y;
    const int b  = bh >> 3;
    const int h  = bh & 7;
    const bool loc = (h >= 4);
    const int hl = h - 4;
    const int row0 = blockIdx.x * 16;

    // load Q tile (16x64 = 256 float4)
    const float4* qsrc = (const float4*)(qg + (((size_t)bh * NNq + row0) * 64));
    ((float4*)qsh)[tid] = qsrc[tid];
    if (tid < 16) rowc[tid] = loc ? g_rowadd[((size_t)(b * 4 + hl)) * NNq + row0 + tid] : 0.f;
    __syncthreads();

    const int r0 = warp * 2, r1 = r0 + 1;
    const int q0 = row0 + r0, q1 = row0 + r1;
    const int* mrow0 = mask + ((size_t)b * NNq + q0) * NNq;
    const int* mrow1 = mask + ((size_t)b * NNq + q1) * NNq;

    // ---------- Stage A: scores ----------
    const float4* kbase = (const float4*)(kg + ((size_t)bh * NNq) * 64);
    for (int t = 0; t < 8; ++t) {
        const int kb = t * 128;
        // cooperative K tile load (128 keys x 64 dims)
        const float4* gk = kbase + (size_t)kb * 16;
        #pragma unroll
        for (int i = tid; i < 2048; i += 256) {
            int kk = i >> 4, d4 = i & 15;
            *((float4*)(ksh + kk * KSTRIDE + d4 * 4)) = gk[i];
        }
        __syncthreads();

        float acc0[4] = {0.f, 0.f, 0.f, 0.f};
        float acc1[4] = {0.f, 0.f, 0.f, 0.f};
        const float* q0p = qsh + r0 * 64;
        const float* q1p = qsh + r1 * 64;
        #pragma unroll
        for (int d = 0; d < 64; d += 4) {
            float4 qa = *(const float4*)(q0p + d);
            float4 qb = *(const float4*)(q1p + d);
            #pragma unroll
            for (int j = 0; j < 4; ++j) {
                float4 kv = *(const float4*)(ksh + (lane + 32 * j) * KSTRIDE + d);
                acc0[j] += qa.x * kv.x + qa.y * kv.y + qa.z * kv.z + qa.w * kv.w;
                acc1[j] += qb.x * kv.x + qb.y * kv.y + qb.z * kv.z + qb.w * kv.w;
            }
        }
        #pragma unroll
        for (int j = 0; j < 4; ++j) {
            int kk = kb + lane + 32 * j;
            float s0 = acc0[j] * SCALEq;
            float s1 = acc1[j] * SCALEq;
            if (loc) {
                float ca  = g_coladd[((size_t)(b * 4 + hl)) * NNq + kk];
                float rr0 = g_R[hl * 2047 + kk - q0 + 1023];
                float rr1 = g_R[hl * 2047 + kk - q1 + 1023];
                s0 += rr0 + ca + rowc[r0];
                s1 += rr1 + ca + rowc[r1];
            }
            int m0 = mrow0[kk];
            int m1 = mrow1[kk];
            ssh[r0 * 1024 + kk] = m0 ? s0 : NEGBIG;
            ssh[r1 * 1024 + kk] = m1 ? s1 : NEGBIG;
        }
        __syncthreads();
    }

    // ---------- Stage B: softmax (per warp, its 2 rows) ----------
    #pragma unroll 1
    for (int rr = 0; rr < 2; ++rr) {
        const int r = r0 + rr;
        const int qq = row0 + r;
        float* srow = ssh + r * 1024;
        float sc[32];
        float mx = -3.4e38f;
        #pragma unroll
        for (int j = 0; j < 32; ++j) {
            sc[j] = srow[lane + 32 * j];
            mx = fmaxf(mx, sc[j]);
        }
        #pragma unroll
        for (int o = 16; o > 0; o >>= 1) mx = fmaxf(mx, __shfl_xor_sync(0xffffffffu, mx, o));
        float sum = 0.f;
        #pragma unroll
        for (int j = 0; j < 32; ++j) {
            sc[j] = __expf(sc[j] - mx);
            sum += sc[j];
        }
        #pragma unroll
        for (int o = 16; o > 0; o >>= 1) sum += __shfl_xor_sync(0xffffffffu, sum, o);
        float inv = 1.0f / sum;

        float* pgl = nullptr;
        if (pg) {
            pgl = (h < 4) ? pg + (((size_t)(b * 4 + h)  * NNq + qq) * NNq)
                          : pl + (((size_t)(b * 4 + hl) * NNq + qq) * NNq);
        }
        #pragma unroll
        for (int j = 0; j < 32; ++j) {
            float p = sc[j] * inv;
            srow[lane + 32 * j] = p;
            if (pgl) pgl[lane + 32 * j] = p;
        }
    }
    __syncthreads();

    // ---------- Stage C: out = P @ V ----------
    float o00 = 0.f, o01 = 0.f, o10 = 0.f, o11 = 0.f;
    const int d0 = lane * 2;
    const float4* vbase = (const float4*)(vg + ((size_t)bh * NNq) * 64);
    for (int t = 0; t < 8; ++t) {
        const int kb = t * 128;
        const float4* gv = vbase + (size_t)kb * 16;
        #pragma unroll
        for (int i = tid; i < 2048; i += 256) {
            int kk = i >> 4, d4 = i & 15;
            *((float4*)(ksh + kk * KSTRIDE + d4 * 4)) = gv[i];
        }
        __syncthreads();

        const float* p0row = ssh + r0 * 1024 + kb;
        const float* p1row = ssh + r1 * 1024 + kb;
        #pragma unroll 4
        for (int kk = 0; kk < 128; kk += 4) {
            float4 pa = *(const float4*)(p0row + kk);
            float4 pb = *(const float4*)(p1row + kk);
            float2 v0 = *(const float2*)(ksh + (kk + 0) * KSTRIDE + d0);
            float2 v1 = *(const float2*)(ksh + (kk + 1) * KSTRIDE + d0);
            float2 v2 = *(const float2*)(ksh + (kk + 2) * KSTRIDE + d0);
            float2 v3 = *(const float2*)(ksh + (kk + 3) * KSTRIDE + d0);
            o00 += pa.x * v0.x; o01 += pa.x * v0.y;
            o10 += pb.x * v0.x; o11 += pb.x * v0.y;
            o00 += pa.y * v1.x; o01 += pa.y * v1.y;
            o10 += pb.y * v1.x; o11 += pb.y * v1.y;
            o00 += pa.z * v2.x; o01 += pa.z * v2.y;
            o10 += pb.z * v2.x; o11 += pb.z * v2.y;
            o00 += pa.w * v3.x; o01 += pa.w * v3.y;
            o10 += pb.w * v3.x; o11 += pb.w * v3.y;
        }
        __syncthreads();
    }

    float* orow0 = out + (((size_t)bh * NNq + q0) * 64);
    float* orow1 = out + (((size_t)bh * NNq + q1) * 64);
    *(float2*)(orow0 + d0) = make_float2(o00, o01);
    *(float2*)(orow1 + d0) = make_float2(o10, o11);
}

extern "C" void kernel_launch(void* const* d_in, const int* in_sizes, int n_in,
                              void* d_out, int out_size) {
    const float* q     = (const float*)d_in[0];
    const float* k     = (const float*)d_in[1];
    const float* v     = (const float*)d_in[2];
    const int*   mask  = (const int*)d_in[3];
    const float* users = (const float*)d_in[4];
    const float* rpt   = (const float*)d_in[5];
    const float* upw   = (const float*)d_in[6];
    const float* upb   = (const float*)d_in[7];
    const float* mlpw  = (const float*)d_in[8];
    const float* mlpb  = (const float*)d_in[9];

    float* out = (float*)d_out;
    const long long OUT_E = 16LL * 8 * 1024 * 64;        // 8,388,608
    const long long PG_E  = 16LL * 4 * 1024 * 1024;      // 67,108,864
    float* pg = nullptr;
    float* pl = nullptr;
    if ((long long)out_size >= OUT_E + 2 * PG_E) {
        pg = out + OUT_E;
        pl = pg + PG_E;
    }

    prep_w2<<<2, 256>>>(upw, upb, mlpw);
    prep_r<<<32, 256>>>(rpt, mlpw);
    prep_rc<<<256, 256>>>(v, users, mlpw, mlpb);

    cudaFuncSetAttribute(attn_kernel, cudaFuncAttributeMaxDynamicSharedMemorySize, SMEM_BYTES);
    dim3 grid(64, 128);  // 64 q-blocks of 16 rows, 128 (b,h) pairs
    attn_kernel<<<grid, 256, SMEM_BYTES>>>(q, k, v, mask, out, pg, pl);
}

// round 5
// speedup vs baseline: 1.2327x; 1.2327x over previous
#include <cuda_runtime.h>

// AdaptAttention: b=16, H=8 (4 global + 4 local), N=1024, DK=64, fp32.
// Outputs concatenated: out (16,8,1024,64), p_attn_g (16,4,1024,1024), p_attn_l (16,4,1024,1024).

#define NNq  1024
#define DKq  64
#define SCALEq 0.125f
#define NEGBIG -1000000000000.0f

// ---- device scratch (no allocations allowed) ----
__device__ float g_W2[512 * 4];
__device__ float g_bias2[4];
__device__ float g_R[4 * 2047];
__device__ float g_rowadd[16 * 4 * 1024];
__device__ float g_coladd[16 * 4 * 1024];

__global__ void prep_w2(const float* __restrict__ upw,
                        const float* __restrict__ upb,
                        const float* __restrict__ mlpw) {
    int t = blockIdx.x * blockDim.x + threadIdx.x;
    if (t < 512) {
        const float* row = upw + (size_t)t * 256;
        float s0 = 0.f, s1 = 0.f, s2 = 0.f, s3 = 0.f;
        for (int d = 0; d < 64; ++d) {
            s0 += row[d]       * mlpw[d];
            s1 += row[64 + d]  * mlpw[64 + d];
            s2 += row[128 + d] * mlpw[128 + d];
            s3 += row[192 + d] * mlpw[192 + d];
        }
        g_W2[t * 4 + 0] = s0;
        g_W2[t * 4 + 1] = s1;
        g_W2[t * 4 + 2] = s2;
        g_W2[t * 4 + 3] = s3;
    }
    if (t < 4) {
        float s = 0.f;
        for (int d = 0; d < 64; ++d) s += upb[t * 64 + d] * mlpw[t * 64 + d];
        g_bias2[t] = s;
    }
}

__global__ void prep_r(const float* __restrict__ rpt,
                       const float* __restrict__ mlpw) {
    int idx = blockIdx.x * blockDim.x + threadIdx.x;
    if (idx >= 4 * 2047) return;
    int hl = idx / 2047, delta = idx % 2047;
    const float* row = rpt + (size_t)delta * 256 + hl * 64;
    const float* w = mlpw + hl * 64;
    float s = 0.f;
    for (int d = 0; d < 64; ++d) s += row[d] * w[d];
    g_R[idx] = s;
}

__global__ void prep_rc(const float* __restrict__ value,
                        const float* __restrict__ users,
                        const float* __restrict__ mlpw,
                        const float* __restrict__ mlpb) {
    int idx = blockIdx.x * blockDim.x + threadIdx.x;
    int i  = idx & 1023;
    int hl = (idx >> 10) & 3;
    int b  = idx >> 12;
    const float* vrow = value + (((size_t)(b * 8 + 4 + hl)) * NNq + i) * 64;
    const float* w = mlpw + hl * 64;
    float vv = 0.f;
    for (int d = 0; d < 64; ++d) vv += vrow[d] * w[d];
    const float* urow = users + ((size_t)b * NNq + i) * 512;
    float uu = 0.f;
    for (int c = 0; c < 512; ++c) uu += urow[c] * g_W2[c * 4 + hl];
    g_coladd[idx] = vv;
    g_rowadd[idx] = vv + uu + g_bias2[hl] + mlpb[hl];
}

// ---- main attention kernel ----
// CTA: 256 threads (8 warps), 16 q rows. Warp = (rgrp, khalf): 4 rows x 64-key half.
// smem: ksh[128][68], ssh[16][1024], qsh[16][64] (reused as osq in stage C), rowc[16].
#define KSTRIDE 68
#define SM_KSH  (128 * KSTRIDE)
#define SM_SSH  (16 * 1024)
#define SM_QSH  (16 * 64)
#define SMEM_FLOATS (SM_KSH + SM_SSH + SM_QSH + 32)
#define SMEM_BYTES  (SMEM_FLOATS * 4)        // 104,576 B -> 2 CTAs/SM

__global__ void __launch_bounds__(256, 2)
attn_kernel(const float* __restrict__ qg, const float* __restrict__ kg,
            const float* __restrict__ vg, const int* __restrict__ mask,
            float* __restrict__ out, float* __restrict__ pg, float* __restrict__ pl) {
    extern __shared__ float sm[];
    float* ksh  = sm;
    float* ssh  = sm + SM_KSH;
    float* qsh  = sm + SM_KSH + SM_SSH;   // stage A: q tile; stage C: partial-out buffer
    float* rowc = sm + SM_KSH + SM_SSH + SM_QSH;

    const int tid  = threadIdx.x;
    const int warp = tid >> 5;
    const int lane = tid & 31;
    const int bh = blockIdx.y;
    const int b  = bh >> 3;
    const int h  = bh & 7;
    const bool loc = (h >= 4);
    const int hl = h - 4;
    const int row0 = blockIdx.x * 16;

    const int rgrp  = warp & 3;          // row group: rows rgrp*4 .. rgrp*4+3
    const int khalf = warp >> 2;         // key half within 128-key tile
    const int r0 = rgrp * 4;

    // load Q tile (16x64 = 256 float4)
    const float4* qsrc = (const float4*)(qg + (((size_t)bh * NNq + row0) * 64));
    ((float4*)qsh)[tid] = qsrc[tid];
    if (tid < 16) rowc[tid] = loc ? g_rowadd[((size_t)(b * 4 + hl)) * NNq + row0 + tid] : 0.f;
    __syncthreads();

    const int* mrow0 = mask + ((size_t)b * NNq + row0 + r0 + 0) * NNq;
    const int* mrow1 = mask + ((size_t)b * NNq + row0 + r0 + 1) * NNq;
    const int* mrow2 = mask + ((size_t)b * NNq + row0 + r0 + 2) * NNq;
    const int* mrow3 = mask + ((size_t)b * NNq + row0 + r0 + 3) * NNq;

    // ---------- Stage A: scores ----------
    const float4* kbase = (const float4*)(kg + ((size_t)bh * NNq) * 64);
    for (int t = 0; t < 8; ++t) {
        const int kb = t * 128;
        const float4* gk = kbase + (size_t)kb * 16;
        #pragma unroll
        for (int i = tid; i < 2048; i += 256) {
            int kk = i >> 4, d4 = i & 15;
            *((float4*)(ksh + kk * KSTRIDE + d4 * 4)) = gk[i];
        }
        __syncthreads();

        float acc[4][2];
        #pragma unroll
        for (int i = 0; i < 4; ++i) { acc[i][0] = 0.f; acc[i][1] = 0.f; }

        const float* kp0 = ksh + (khalf * 64 + lane) * KSTRIDE;
        const float* kp1 = kp0 + 32 * KSTRIDE;
        #pragma unroll
        for (int d = 0; d < 64; d += 4) {
            float4 kv0 = *(const float4*)(kp0 + d);
            float4 kv1 = *(const float4*)(kp1 + d);
            #pragma unroll
            for (int i = 0; i < 4; ++i) {
                float4 qa = *(const float4*)(qsh + (r0 + i) * 64 + d);
                acc[i][0] += qa.x * kv0.x + qa.y * kv0.y + qa.z * kv0.z + qa.w * kv0.w;
                acc[i][1] += qa.x * kv1.x + qa.y * kv1.y + qa.z * kv1.z + qa.w * kv1.w;
            }
        }

        #pragma unroll
        for (int j = 0; j < 2; ++j) {
            const int kk = kb + khalf * 64 + lane + 32 * j;
            float s0 = acc[0][j] * SCALEq;
            float s1 = acc[1][j] * SCALEq;
            float s2 = acc[2][j] * SCALEq;
            float s3 = acc[3][j] * SCALEq;
            if (loc) {
                float ca = g_coladd[((size_t)(b * 4 + hl)) * NNq + kk];
                const float* Rb = g_R + hl * 2047 + kk + 1023 - row0 - r0;
                s0 += Rb[0]  + ca + rowc[r0 + 0];
                s1 += Rb[-1] + ca + rowc[r0 + 1];
                s2 += Rb[-2] + ca + rowc[r0 + 2];
                s3 += Rb[-3] + ca + rowc[r0 + 3];
            }
            ssh[(r0 + 0) * 1024 + kk] = mrow0[kk] ? s0 : NEGBIG;
            ssh[(r0 + 1) * 1024 + kk] = mrow1[kk] ? s1 : NEGBIG;
            ssh[(r0 + 2) * 1024 + kk] = mrow2[kk] ? s2 : NEGBIG;
            ssh[(r0 + 3) * 1024 + kk] = mrow3[kk] ? s3 : NEGBIG;
        }
        __syncthreads();
    }

    // ---------- Stage B: softmax (warp handles rows 2w, 2w+1) ----------
    #pragma unroll 1
    for (int rr = 0; rr < 2; ++rr) {
        const int r = warp * 2 + rr;
        const int qq = row0 + r;
        float* srow = ssh + r * 1024;
        float sc[32];
        float mx = -3.4e38f;
        #pragma unroll
        for (int j = 0; j < 32; ++j) {
            sc[j] = srow[lane + 32 * j];
            mx = fmaxf(mx, sc[j]);
        }
        #pragma unroll
        for (int o = 16; o > 0; o >>= 1) mx = fmaxf(mx, __shfl_xor_sync(0xffffffffu, mx, o));
        float sum = 0.f;
        #pragma unroll
        for (int j = 0; j < 32; ++j) {
            sc[j] = __expf(sc[j] - mx);
            sum += sc[j];
        }
        #pragma unroll
        for (int o = 16; o > 0; o >>= 1) sum += __shfl_xor_sync(0xffffffffu, sum, o);
        float inv = 1.0f / sum;

        float* pgl = (h < 4) ? pg + (((size_t)(b * 4 + h)  * NNq + qq) * NNq)
                             : pl + (((size_t)(b * 4 + hl) * NNq + qq) * NNq);
        #pragma unroll
        for (int j = 0; j < 32; ++j) {
            float p = sc[j] * inv;
            srow[lane + 32 * j] = p;
            pgl[lane + 32 * j] = p;
        }
    }
    __syncthreads();

    // ---------- Stage C: out = P @ V (warp = 4 rows x key-half) ----------
    float o0x = 0.f, o0y = 0.f, o1x = 0.f, o1y = 0.f;
    float o2x = 0.f, o2y = 0.f, o3x = 0.f, o3y = 0.f;
    const int d0 = lane * 2;
    const float4* vbase = (const float4*)(vg + ((size_t)bh * NNq) * 64);
    for (int t = 0; t < 8; ++t) {
        const int kb = t * 128;
        const float4* gv = vbase + (size_t)kb * 16;
        #pragma unroll
        for (int i = tid; i < 2048; i += 256) {
            int kk = i >> 4, d4 = i & 15;
            *((float4*)(ksh + kk * KSTRIDE + d4 * 4)) = gv[i];
        }
        __syncthreads();

        const float* p0 = ssh + (r0 + 0) * 1024 + kb + khalf * 64;
        const float* p1 = ssh + (r0 + 1) * 1024 + kb + khalf * 64;
        const float* p2 = ssh + (r0 + 2) * 1024 + kb + khalf * 64;
        const float* p3 = ssh + (r0 + 3) * 1024 + kb + khalf * 64;
        const float* vh = ksh + (khalf * 64) * KSTRIDE + d0;
        #pragma unroll 4
        for (int kk = 0; kk < 64; kk += 4) {
            float4 pa = *(const float4*)(p0 + kk);
            float4 pb = *(const float4*)(p1 + kk);
            float4 pc = *(const float4*)(p2 + kk);
            float4 pd = *(const float4*)(p3 + kk);
            float2 v0 = *(const float2*)(vh + (kk + 0) * KSTRIDE);
            float2 v1 = *(const float2*)(vh + (kk + 1) * KSTRIDE);
            float2 v2 = *(const float2*)(vh + (kk + 2) * KSTRIDE);
            float2 v3 = *(const float2*)(vh + (kk + 3) * KSTRIDE);
            o0x += pa.x * v0.x + pa.y * v1.x + pa.z * v2.x + pa.w * v3.x;
            o0y += pa.x * v0.y + pa.y * v1.y + pa.z * v2.y + pa.w * v3.y;
            o1x += pb.x * v0.x + pb.y * v1.x + pb.z * v2.x + pb.w * v3.x;
            o1y += pb.x * v0.y + pb.y * v1.y + pb.z * v2.y + pb.w * v3.y;
            o2x += pc.x * v0.x + pc.y * v1.x + pc.z * v2.x + pc.w * v3.x;
            o2y += pc.x * v0.y + pc.y * v1.y + pc.z * v2.y + pc.w * v3.y;
            o3x += pd.x * v0.x + pd.y * v1.x + pd.z * v2.x + pd.w * v3.x;
            o3y += pd.x * v0.y + pd.y * v1.y + pd.z * v2.y + pd.w * v3.y;
        }
        __syncthreads();
    }

    // reduce across the two key-halves via smem (reuse qsh area)
    if (khalf == 1) {
        *(float2*)(qsh + (r0 + 0) * 64 + d0) = make_float2(o0x, o0y);
        *(float2*)(qsh + (r0 + 1) * 64 + d0) = make_float2(o1x, o1y);
        *(float2*)(qsh + (r0 + 2) * 64 + d0) = make_float2(o2x, o2y);
        *(float2*)(qsh + (r0 + 3) * 64 + d0) = make_float2(o3x, o3y);
    }
    __syncthreads();
    if (khalf == 0) {
        float2 a0 = *(const float2*)(qsh + (r0 + 0) * 64 + d0);
        float2 a1 = *(const float2*)(qsh + (r0 + 1) * 64 + d0);
        float2 a2 = *(const float2*)(qsh + (r0 + 2) * 64 + d0);
        float2 a3 = *(const float2*)(qsh + (r0 + 3) * 64 + d0);
        float* ob = out + (((size_t)bh * NNq + row0 + r0) * 64) + d0;
        *(float2*)(ob + 0 * 64) = make_float2(o0x + a0.x, o0y + a0.y);
        *(float2*)(ob + 1 * 64) = make_float2(o1x + a1.x, o1y + a1.y);
        *(float2*)(ob + 2 * 64) = make_float2(o2x + a2.x, o2y + a2.y);
        *(float2*)(ob + 3 * 64) = make_float2(o3x + a3.x, o3y + a3.y);
    }
}

extern "C" void kernel_launch(void* const* d_in, const int* in_sizes, int n_in,
                              void* d_out, int out_size) {
    const float* q     = (const float*)d_in[0];
    const float* k     = (const float*)d_in[1];
    const float* v     = (const float*)d_in[2];
    const int*   mask  = (const int*)d_in[3];
    const float* users = (const float*)d_in[4];
    const float* rpt   = (const float*)d_in[5];
    const float* upw   = (const float*)d_in[6];
    const float* upb   = (const float*)d_in[7];
    const float* mlpw  = (const float*)d_in[8];
    const float* mlpb  = (const float*)d_in[9];

    float* out = (float*)d_out;
    const long long OUT_E = 16LL * 8 * 1024 * 64;
    const long long PG_E  = 16LL * 4 * 1024 * 1024;
    float* pg = out + OUT_E;
    float* pl = pg + PG_E;

    prep_w2<<<2, 256>>>(upw, upb, mlpw);
    prep_r<<<32, 256>>>(rpt, mlpw);
    prep_rc<<<256, 256>>>(v, users, mlpw, mlpb);

    cudaFuncSetAttribute(attn_kernel, cudaFuncAttributeMaxDynamicSharedMemorySize, SMEM_BYTES);
    dim3 grid(64, 128);
    attn_kernel<<<grid, 256, SMEM_BYTES>>>(q, k, v, mask, out, pg, pl);
}